// round 7
// baseline (speedup 1.0000x reference)
#include <cuda_runtime.h>
#include <cuda_bf16.h>
#include <cstdint>

// out[b,g,k] = sum_d (h[b,g,d]/||h||) * (w[g,d,k]/||w_col||)
// B=512, G=100, D=768, K=100.
// bf16 two-term split, 3-product HMMA, ldmatrix, double-buffered smem.
// CTA tile 64x128 (4 warps, warp 64x32), BKC=32, 3 CTAs/SM, grid 800.
// Pad-column trim: rotated light warp computes only cols 96..103.

#define B_ 512
#define G_ 100
#define D_ 768
#define K_ 100
#define KP 128
#define BKC 32              // k-chunk
#define NCHUNK (D_ / BKC)   // 24
#define LDB 80              // smem row stride bytes (32 bf16 + pad)

#define AH_OFF 0            // 64 x 80 = 5120
#define AL_OFF 5120
#define BH_OFF 10240        // 128 x 80 = 10240
#define BL_OFF 20480
#define STAGE_BYTES 30720

// ---------------- device scratch ----------------
__device__ float g_inv_h[B_ * G_];
__device__ float g_inv_w[G_ * K_];
__device__ __nv_bfloat16 g_wt_hi[(size_t)G_ * KP * D_];
__device__ __nv_bfloat16 g_wt_lo[(size_t)G_ * KP * D_];

// ---------------- helpers ----------------
__device__ __forceinline__ uint32_t smem_u32(const void* p) {
    uint32_t a;
    asm("{ .reg .u64 t; cvta.to.shared.u64 t, %1; cvt.u32.u64 %0, t; }"
        : "=r"(a) : "l"(p));
    return a;
}

#define MMA_BF16(d, a, b0, b1)                                              \
    asm volatile(                                                           \
        "mma.sync.aligned.m16n8k16.row.col.f32.bf16.bf16.f32 "              \
        "{%0,%1,%2,%3}, {%4,%5,%6,%7}, {%8,%9}, {%0,%1,%2,%3};"             \
        : "+f"(d[0]), "+f"(d[1]), "+f"(d[2]), "+f"(d[3])                    \
        : "r"(a[0]), "r"(a[1]), "r"(a[2]), "r"(a[3]), "r"(b0), "r"(b1))

#define LDSM4(r, addr)                                                      \
    asm volatile("ldmatrix.sync.aligned.m8n8.x4.shared.b16 "                \
                 "{%0,%1,%2,%3}, [%4];"                                     \
                 : "=r"((r)[0]), "=r"((r)[1]), "=r"((r)[2]), "=r"((r)[3])   \
                 : "r"(addr))

#define CP16(dst, src)                                                      \
    asm volatile("cp.async.cg.shared.global [%0], [%1], 16;"                \
                 :: "r"(dst), "l"(src) : "memory")
#define CP_COMMIT() asm volatile("cp.async.commit_group;" ::: "memory")
#define CP_WAIT0()  asm volatile("cp.async.wait_group 0;" ::: "memory")

// ---------------------------------------------------------------------------
__global__ void norm_h_kernel(const float* __restrict__ h) {
    int warp = (blockIdx.x * blockDim.x + threadIdx.x) >> 5;
    int lane = threadIdx.x & 31;
    if (warp >= B_ * G_) return;
    const float4* p = reinterpret_cast<const float4*>(h + (size_t)warp * D_);
    float s = 0.f;
#pragma unroll
    for (int t = 0; t < 6; t++) {
        float4 v = p[lane + 32 * t];
        s += v.x * v.x + v.y * v.y + v.z * v.z + v.w * v.w;
    }
#pragma unroll
    for (int o = 16; o; o >>= 1) s += __shfl_xor_sync(0xffffffffu, s, o);
    if (lane == 0) g_inv_h[warp] = 1.0f / fmaxf(sqrtf(s), 1e-12f);
}

__global__ void norm_w_kernel(const float* __restrict__ w) {
    __shared__ float partial[4][128];
    int g = blockIdx.x;
    int k = threadIdx.x & 127;
    int c = threadIdx.x >> 7;
    float s = 0.f;
    if (k < K_) {
        const float* base = w + (size_t)g * D_ * K_ + (size_t)c * 192 * K_ + k;
#pragma unroll 8
        for (int d = 0; d < 192; d++) {
            float v = base[(size_t)d * K_];
            s += v * v;
        }
    }
    partial[c][k] = s;
    __syncthreads();
    if (c == 0 && k < K_) {
        float t = partial[0][k] + partial[1][k] + partial[2][k] + partial[3][k];
        g_inv_w[g * K_ + k] = 1.0f / fmaxf(sqrtf(t), 1e-12f);
    }
}

__global__ void split_w_kernel(const float* __restrict__ w) {
    __shared__ float ws[64][104];
    const int dc = blockIdx.x;
    const int g  = blockIdx.y;
    const int tid = threadIdx.x;
    const float* src = w + (size_t)g * D_ * K_ + (size_t)dc * 64 * K_;
#pragma unroll
    for (int i = 0; i < 25; i++) {
        int idx = tid + 256 * i;
        ws[idx / K_][idx % K_] = src[idx];
    }
    __syncthreads();
    const int k  = tid >> 1;
    const int d0 = (tid & 1) * 32;
    float invw = (k < K_) ? g_inv_w[g * K_ + k] : 0.f;
    __nv_bfloat16 hb[32], lb[32];
#pragma unroll
    for (int j = 0; j < 32; j++) {
        float x = (k < K_) ? ws[d0 + j][k] * invw : 0.f;
        __nv_bfloat16 hi = __float2bfloat16(x);
        hb[j] = hi;
        lb[j] = __float2bfloat16(x - __bfloat162float(hi));
    }
    size_t base = ((size_t)g * KP + k) * D_ + (size_t)dc * 64 + d0;
    uint4* dh = reinterpret_cast<uint4*>(g_wt_hi + base);
    uint4* dl = reinterpret_cast<uint4*>(g_wt_lo + base);
#pragma unroll
    for (int q = 0; q < 4; q++) {
        dh[q] = *reinterpret_cast<const uint4*>(hb + q * 8);
        dl[q] = *reinterpret_cast<const uint4*>(lb + q * 8);
    }
}

// ---------------------------------------------------------------------------
// HMMA GEMM. CTA = (g, 64 rows). 4 warps, warp tile 64x32 (rotated n-map).
// Light warp (cols 96..127) computes only nf=0 (cols 96..103).
// ---------------------------------------------------------------------------
__global__ __launch_bounds__(128, 3)
void gemm_hmma_kernel(const float* __restrict__ h, float* __restrict__ out) {
    extern __shared__ char smem[];
    const uint32_t sb = smem_u32(smem);
    const int tid  = threadIdx.x;
    const int lane = tid & 31;
    const int warp = tid >> 5;
    const int g  = blockIdx.y;
    const int m0 = blockIdx.x * 64;
    // rotated n-mapping: co-resident CTAs put the light warp on different SMSPs
    const int nw = (warp + blockIdx.x) & 3;
    const int nfc = (nw == 3) ? 1 : 4;   // frag count (cols >= 104 are padding)
    const int ngc = (nw == 3) ? 1 : 2;   // 16-col B groups to load

    // ---- global load mapping ----
    // A: 64 rows, 2 threads/row, 16 fp32 each
    const int arow = tid >> 1;
    const int half = tid & 1;
    const float* gA = h + ((size_t)(m0 + arow) * G_ + g) * D_ + half * 16;
    const float invh = g_inv_h[(size_t)(m0 + arow) * G_ + g];
    // B: 128 rows, 1 thread/row, 32 bf16 (64B) per tile
    const char* gBh = reinterpret_cast<const char*>(
        g_wt_hi + ((size_t)g * KP + tid) * D_);
    const char* gBl = reinterpret_cast<const char*>(
        g_wt_lo + ((size_t)g * KP + tid) * D_);

    const uint32_t srowA = arow * LDB + half * 32;
    const uint32_t srowB = tid * LDB;

    // ldmatrix base addresses (stage-relative)
    const uint32_t a_lm = (lane & 15) * LDB + (lane >> 4) * 16;
    const uint32_t b_lm = (nw * 32 + (lane & 7) + ((lane >> 4) & 1) * 8) * LDB
                        + ((lane >> 3) & 1) * 16;

    float acc[4][4][4];   // [mt][nf][reg]
#pragma unroll
    for (int mt = 0; mt < 4; mt++)
#pragma unroll
        for (int nf = 0; nf < 4; nf++)
#pragma unroll
            for (int r = 0; r < 4; r++) acc[mt][nf][r] = 0.f;

    // ---- A convert+store: 16 fp32 -> hi/lo bf16 (32B each) ----
    auto store_A = [&](const float4* av, uint32_t stage) {
        uint32_t uh[8], ul[8];
#pragma unroll
        for (int i = 0; i < 4; i++) {
            float x0 = av[i].x * invh, x1 = av[i].y * invh;
            float x2 = av[i].z * invh, x3 = av[i].w * invh;
            __nv_bfloat162 h0 = __float22bfloat162_rn(make_float2(x0, x1));
            __nv_bfloat162 h1 = __float22bfloat162_rn(make_float2(x2, x3));
            float2 f0 = __bfloat1622float2(h0), f1 = __bfloat1622float2(h1);
            __nv_bfloat162 l0 = __float22bfloat162_rn(make_float2(x0 - f0.x, x1 - f0.y));
            __nv_bfloat162 l1 = __float22bfloat162_rn(make_float2(x2 - f1.x, x3 - f1.y));
            uh[i * 2]     = *reinterpret_cast<uint32_t*>(&h0);
            uh[i * 2 + 1] = *reinterpret_cast<uint32_t*>(&h1);
            ul[i * 2]     = *reinterpret_cast<uint32_t*>(&l0);
            ul[i * 2 + 1] = *reinterpret_cast<uint32_t*>(&l1);
        }
        asm volatile("st.shared.v4.b32 [%0], {%1,%2,%3,%4};"
            :: "r"(stage + AH_OFF + srowA), "r"(uh[0]), "r"(uh[1]), "r"(uh[2]), "r"(uh[3]) : "memory");
        asm volatile("st.shared.v4.b32 [%0], {%1,%2,%3,%4};"
            :: "r"(stage + AH_OFF + srowA + 16), "r"(uh[4]), "r"(uh[5]), "r"(uh[6]), "r"(uh[7]) : "memory");
        asm volatile("st.shared.v4.b32 [%0], {%1,%2,%3,%4};"
            :: "r"(stage + AL_OFF + srowA), "r"(ul[0]), "r"(ul[1]), "r"(ul[2]), "r"(ul[3]) : "memory");
        asm volatile("st.shared.v4.b32 [%0], {%1,%2,%3,%4};"
            :: "r"(stage + AL_OFF + srowA + 16), "r"(ul[4]), "r"(ul[5]), "r"(ul[6]), "r"(ul[7]) : "memory");
    };

    auto cp_B = [&](int c, uint32_t stage) {
#pragma unroll
        for (int i = 0; i < 4; i++) {
            CP16(stage + BH_OFF + srowB + i * 16, gBh + (size_t)c * 64 + i * 16);
            CP16(stage + BL_OFF + srowB + i * 16, gBl + (size_t)c * 64 + i * 16);
        }
    };

    // ---- prologue: fill stage 0 ----
    {
        float4 av[4];
#pragma unroll
        for (int i = 0; i < 4; i++)
            av[i] = *reinterpret_cast<const float4*>(gA + i * 4);
        cp_B(0, sb);
        CP_COMMIT();
        store_A(av, sb);
        CP_WAIT0();
    }
    __syncthreads();

    for (int c = 0; c < NCHUNK; c++) {
        const uint32_t stage  = sb + (uint32_t)(c & 1) * STAGE_BYTES;
        const uint32_t nstage = sb + (uint32_t)((c + 1) & 1) * STAGE_BYTES;

        float4 av[4];
        if (c + 1 < NCHUNK) {
#pragma unroll
            for (int i = 0; i < 4; i++)
                av[i] = *reinterpret_cast<const float4*>(gA + (c + 1) * BKC + i * 4);
            cp_B(c + 1, nstage);
            CP_COMMIT();
        }

        // ---- compute current chunk: 2 k16-steps ----
#pragma unroll
        for (int ks = 0; ks < 2; ks++) {
            const uint32_t ko = ks * 32;
            uint32_t bh[2][4], bl[2][4];
#pragma unroll
            for (int ng = 0; ng < 2; ng++) {
                if (ng < ngc) {
                    LDSM4(bh[ng], stage + BH_OFF + b_lm + ng * (16 * LDB) + ko);
                    LDSM4(bl[ng], stage + BL_OFF + b_lm + ng * (16 * LDB) + ko);
                }
            }
#pragma unroll
            for (int mt = 0; mt < 4; mt++) {
                uint32_t ah[4], al[4];
                LDSM4(ah, stage + AH_OFF + a_lm + mt * (16 * LDB) + ko);
                LDSM4(al, stage + AL_OFF + a_lm + mt * (16 * LDB) + ko);
#pragma unroll
                for (int nf = 0; nf < 4; nf++)
                    if (nf < nfc)
                        MMA_BF16(acc[mt][nf], ah,
                                 bh[nf >> 1][(nf & 1) * 2], bh[nf >> 1][(nf & 1) * 2 + 1]);
#pragma unroll
                for (int nf = 0; nf < 4; nf++)
                    if (nf < nfc)
                        MMA_BF16(acc[mt][nf], ah,
                                 bl[nf >> 1][(nf & 1) * 2], bl[nf >> 1][(nf & 1) * 2 + 1]);
#pragma unroll
                for (int nf = 0; nf < 4; nf++)
                    if (nf < nfc)
                        MMA_BF16(acc[mt][nf], al,
                                 bh[nf >> 1][(nf & 1) * 2], bh[nf >> 1][(nf & 1) * 2 + 1]);
            }
        }

        if (c + 1 < NCHUNK) {
            store_A(av, nstage);
            CP_WAIT0();
        }
        __syncthreads();
    }

    // ---- epilogue ----
#pragma unroll
    for (int mt = 0; mt < 4; mt++) {
        const int row = m0 + mt * 16 + (lane >> 2);
#pragma unroll
        for (int nf = 0; nf < 4; nf++) {
            if (nf < nfc) {
                const int col = nw * 32 + nf * 8 + (lane & 3) * 2;
                if (col < K_) {
                    float2 v0 = {acc[mt][nf][0], acc[mt][nf][1]};
                    float2 v1 = {acc[mt][nf][2], acc[mt][nf][3]};
                    *reinterpret_cast<float2*>(out + ((size_t)row * G_ + g) * K_ + col) = v0;
                    *reinterpret_cast<float2*>(out + ((size_t)(row + 8) * G_ + g) * K_ + col) = v1;
                }
            }
        }
    }
}

// ---------------------------------------------------------------------------
extern "C" void kernel_launch(void* const* d_in, const int* in_sizes, int n_in,
                              void* d_out, int out_size) {
    const float* h = (const float*)d_in[0];   // [512,100,768]
    const float* w = (const float*)d_in[1];   // [100,768,100]
    float* out = (float*)d_out;               // [512,100,100]
    (void)in_sizes; (void)n_in; (void)out_size;

    const int smem_bytes = 2 * STAGE_BYTES;   // 61440 per CTA -> 3 CTAs/SM
    cudaFuncSetAttribute(gemm_hmma_kernel,
                         cudaFuncAttributeMaxDynamicSharedMemorySize, smem_bytes);

    norm_h_kernel<<<(B_ * G_) / 8, 256>>>(h);
    norm_w_kernel<<<G_, 512>>>(w);
    split_w_kernel<<<dim3(12, G_), 256>>>(w);
    dim3 grid(B_ / 64, G_);
    gemm_hmma_kernel<<<grid, 128, smem_bytes>>>(h, out);
}

// round 8
// speedup vs baseline: 1.1161x; 1.1161x over previous
#include <cuda_runtime.h>
#include <cuda_bf16.h>
#include <cstdint>

// out[b,g,k] = sum_d (h[b,g,d]/||h||) * (w[g,d,k]/||w_col||)
// B=512, G=100, D=768, K=100.
// bf16 two-term split, 3-product HMMA, ldmatrix, double-buffered smem.
// R6 shape (128x128 CTA, 8 warps, warp 64x32, BKC=32, 2 CTAs/SM) +
// rotated light-warp trim (cols 104..127 skipped) + B rows 112..127 skipped.

#define B_ 512
#define G_ 100
#define D_ 768
#define K_ 100
#define KP 128
#define BKC 32              // k-chunk
#define NCHUNK (D_ / BKC)   // 24
#define LDB 80              // smem row stride bytes (32 bf16 + pad)

#define AH_OFF 0
#define AL_OFF 10240
#define BH_OFF 20480
#define BL_OFF 30720
#define STAGE_BYTES 40960

// ---------------- device scratch ----------------
__device__ float g_inv_h[B_ * G_];
__device__ __nv_bfloat16 g_wt_hi[(size_t)G_ * KP * D_];
__device__ __nv_bfloat16 g_wt_lo[(size_t)G_ * KP * D_];

// ---------------- helpers ----------------
__device__ __forceinline__ uint32_t smem_u32(const void* p) {
    uint32_t a;
    asm("{ .reg .u64 t; cvta.to.shared.u64 t, %1; cvt.u32.u64 %0, t; }"
        : "=r"(a) : "l"(p));
    return a;
}

#define MMA_BF16(d, a, b0, b1)                                              \
    asm volatile(                                                           \
        "mma.sync.aligned.m16n8k16.row.col.f32.bf16.bf16.f32 "              \
        "{%0,%1,%2,%3}, {%4,%5,%6,%7}, {%8,%9}, {%0,%1,%2,%3};"             \
        : "+f"(d[0]), "+f"(d[1]), "+f"(d[2]), "+f"(d[3])                    \
        : "r"(a[0]), "r"(a[1]), "r"(a[2]), "r"(a[3]), "r"(b0), "r"(b1))

#define LDSM4(r, addr)                                                      \
    asm volatile("ldmatrix.sync.aligned.m8n8.x4.shared.b16 "                \
                 "{%0,%1,%2,%3}, [%4];"                                     \
                 : "=r"((r)[0]), "=r"((r)[1]), "=r"((r)[2]), "=r"((r)[3])   \
                 : "r"(addr))

#define CP16(dst, src)                                                      \
    asm volatile("cp.async.cg.shared.global [%0], [%1], 16;"                \
                 :: "r"(dst), "l"(src) : "memory")
#define CP_COMMIT() asm volatile("cp.async.commit_group;" ::: "memory")
#define CP_WAIT0()  asm volatile("cp.async.wait_group 0;" ::: "memory")

// ---------------------------------------------------------------------------
__global__ void norm_h_kernel(const float* __restrict__ h) {
    int warp = (blockIdx.x * blockDim.x + threadIdx.x) >> 5;
    int lane = threadIdx.x & 31;
    if (warp >= B_ * G_) return;
    const float4* p = reinterpret_cast<const float4*>(h + (size_t)warp * D_);
    float s = 0.f;
#pragma unroll
    for (int t = 0; t < 6; t++) {
        float4 v = p[lane + 32 * t];
        s += v.x * v.x + v.y * v.y + v.z * v.z + v.w * v.w;
    }
#pragma unroll
    for (int o = 16; o; o >>= 1) s += __shfl_xor_sync(0xffffffffu, s, o);
    if (lane == 0) g_inv_h[warp] = 1.0f / fmaxf(sqrtf(s), 1e-12f);
}

// ---------------------------------------------------------------------------
// Fused W prep: per-group inv_w (smem) + normalize/split/transpose to scratch.
// One block per g, 256 threads.
// ---------------------------------------------------------------------------
__global__ void prep_w_kernel(const float* __restrict__ w) {
    __shared__ float part[2][128];
    __shared__ float invw_s[128];
    __shared__ float ws[64][104];
    const int g   = blockIdx.x;
    const int tid = threadIdx.x;

    // ---- phase 1: inv_w[k] ----
    {
        int k = tid & 127;
        int c = tid >> 7;                     // 0..1, 384 d each
        float s = 0.f;
        if (k < K_) {
            const float* base = w + (size_t)g * D_ * K_ + (size_t)c * 384 * K_ + k;
#pragma unroll 8
            for (int d = 0; d < 384; d++) {
                float v = base[(size_t)d * K_];
                s += v * v;
            }
        }
        part[c][k] = s;
        __syncthreads();
        if (c == 0)
            invw_s[k] = (k < K_)
                ? 1.0f / fmaxf(sqrtf(part[0][k] + part[1][k]), 1e-12f) : 0.f;
        __syncthreads();
    }

    // ---- phase 2: split + transpose, 12 chunks of 64 d ----
    const int k  = tid >> 1;
    const int d0 = (tid & 1) * 32;
    const float invw = invw_s[k < 128 ? k : 0] * (k < K_ ? 1.f : 0.f);
    for (int dc = 0; dc < 12; dc++) {
        const float* src = w + (size_t)g * D_ * K_ + (size_t)dc * 64 * K_;
#pragma unroll
        for (int i = 0; i < 25; i++) {
            int idx = tid + 256 * i;
            ws[idx / K_][idx % K_] = src[idx];
        }
        __syncthreads();

        __nv_bfloat16 hb[32], lb[32];
#pragma unroll
        for (int j = 0; j < 32; j++) {
            float x = (k < K_) ? ws[d0 + j][k] * invw : 0.f;
            __nv_bfloat16 hi = __float2bfloat16(x);
            hb[j] = hi;
            lb[j] = __float2bfloat16(x - __bfloat162float(hi));
        }
        size_t base = ((size_t)g * KP + k) * D_ + (size_t)dc * 64 + d0;
        uint4* dh = reinterpret_cast<uint4*>(g_wt_hi + base);
        uint4* dl = reinterpret_cast<uint4*>(g_wt_lo + base);
#pragma unroll
        for (int qq = 0; qq < 4; qq++) {
            dh[qq] = *reinterpret_cast<const uint4*>(hb + qq * 8);
            dl[qq] = *reinterpret_cast<const uint4*>(lb + qq * 8);
        }
        __syncthreads();
    }
}

// ---------------------------------------------------------------------------
// HMMA GEMM. CTA = (g, 128 rows), 8 warps: mw = warp&1 (64 rows),
// nw = ((warp>>1)+bx)&3 (32 cols, rotated). Warp tile 64x32.
// Light warp (nw==3): only nf=0 (cols 96..103). B rows 112..127 never loaded.
// ---------------------------------------------------------------------------
__global__ __launch_bounds__(256, 2)
void gemm_hmma_kernel(const float* __restrict__ h, float* __restrict__ out) {
    extern __shared__ char smem[];
    const uint32_t sb = smem_u32(smem);
    const int tid  = threadIdx.x;
    const int lane = tid & 31;
    const int warp = tid >> 5;
    const int mw = warp & 1;
    const int nw = ((warp >> 1) + blockIdx.x) & 3;   // rotated n-mapping
    const int nfc = (nw == 3) ? 1 : 4;
    const int ngc = (nw == 3) ? 1 : 2;
    const int g  = blockIdx.y;
    const int m0 = blockIdx.x * 128;

    // ---- global load mapping: 2 threads per row, 16 elems each ----
    const int arow = tid >> 1;
    const int half = tid & 1;
    const float* gA = h + ((size_t)(m0 + arow) * G_ + g) * D_ + half * 16;
    const float invh = g_inv_h[(size_t)(m0 + arow) * G_ + g];
    const char* gBh = reinterpret_cast<const char*>(
        g_wt_hi + ((size_t)g * KP + arow) * D_) + half * 32;
    const char* gBl = reinterpret_cast<const char*>(
        g_wt_lo + ((size_t)g * KP + arow) * D_) + half * 32;
    const bool bload = (arow < 112);   // rows 112..127 never read (trim)

    const uint32_t srow = arow * LDB + half * 32;

    // ldmatrix base addresses (stage-relative)
    const uint32_t a_lm = (mw * 64 + (lane & 15)) * LDB + (lane >> 4) * 16;
    const uint32_t b_lm = (nw * 32 + (lane & 7) + ((lane >> 4) & 1) * 8) * LDB
                        + ((lane >> 3) & 1) * 16;

    float acc[4][4][4];   // [mt][nf][reg]
#pragma unroll
    for (int mt = 0; mt < 4; mt++)
#pragma unroll
        for (int nf = 0; nf < 4; nf++)
#pragma unroll
            for (int r = 0; r < 4; r++) acc[mt][nf][r] = 0.f;

    // ---- A convert+store: 16 fp32 -> hi/lo bf16 (32B each) ----
    auto store_A = [&](const float4* av, uint32_t stage) {
        uint32_t uh[8], ul[8];
#pragma unroll
        for (int i = 0; i < 4; i++) {
            float x0 = av[i].x * invh, x1 = av[i].y * invh;
            float x2 = av[i].z * invh, x3 = av[i].w * invh;
            __nv_bfloat162 h0 = __float22bfloat162_rn(make_float2(x0, x1));
            __nv_bfloat162 h1 = __float22bfloat162_rn(make_float2(x2, x3));
            float2 f0 = __bfloat1622float2(h0), f1 = __bfloat1622float2(h1);
            __nv_bfloat162 l0 = __float22bfloat162_rn(make_float2(x0 - f0.x, x1 - f0.y));
            __nv_bfloat162 l1 = __float22bfloat162_rn(make_float2(x2 - f1.x, x3 - f1.y));
            uh[i * 2]     = *reinterpret_cast<uint32_t*>(&h0);
            uh[i * 2 + 1] = *reinterpret_cast<uint32_t*>(&h1);
            ul[i * 2]     = *reinterpret_cast<uint32_t*>(&l0);
            ul[i * 2 + 1] = *reinterpret_cast<uint32_t*>(&l1);
        }
        asm volatile("st.shared.v4.b32 [%0], {%1,%2,%3,%4};"
            :: "r"(stage + AH_OFF + srow), "r"(uh[0]), "r"(uh[1]), "r"(uh[2]), "r"(uh[3]) : "memory");
        asm volatile("st.shared.v4.b32 [%0], {%1,%2,%3,%4};"
            :: "r"(stage + AH_OFF + srow + 16), "r"(uh[4]), "r"(uh[5]), "r"(uh[6]), "r"(uh[7]) : "memory");
        asm volatile("st.shared.v4.b32 [%0], {%1,%2,%3,%4};"
            :: "r"(stage + AL_OFF + srow), "r"(ul[0]), "r"(ul[1]), "r"(ul[2]), "r"(ul[3]) : "memory");
        asm volatile("st.shared.v4.b32 [%0], {%1,%2,%3,%4};"
            :: "r"(stage + AL_OFF + srow + 16), "r"(ul[4]), "r"(ul[5]), "r"(ul[6]), "r"(ul[7]) : "memory");
    };

    auto cp_B = [&](int c, uint32_t stage) {
        if (bload) {
            CP16(stage + BH_OFF + srow,      gBh + (size_t)c * 64);
            CP16(stage + BH_OFF + srow + 16, gBh + (size_t)c * 64 + 16);
            CP16(stage + BL_OFF + srow,      gBl + (size_t)c * 64);
            CP16(stage + BL_OFF + srow + 16, gBl + (size_t)c * 64 + 16);
        }
    };

    // ---- prologue: fill stage 0 ----
    {
        float4 av[4];
#pragma unroll
        for (int i = 0; i < 4; i++)
            av[i] = *reinterpret_cast<const float4*>(gA + i * 4);
        cp_B(0, sb);
        CP_COMMIT();
        store_A(av, sb);
        CP_WAIT0();
    }
    __syncthreads();

    for (int c = 0; c < NCHUNK; c++) {
        const uint32_t stage  = sb + (uint32_t)(c & 1) * STAGE_BYTES;
        const uint32_t nstage = sb + (uint32_t)((c + 1) & 1) * STAGE_BYTES;

        float4 av[4];
        if (c + 1 < NCHUNK) {
#pragma unroll
            for (int i = 0; i < 4; i++)
                av[i] = *reinterpret_cast<const float4*>(gA + (c + 1) * BKC + i * 4);
            cp_B(c + 1, nstage);
            CP_COMMIT();
        }

        // ---- compute current chunk: 2 k16-steps ----
#pragma unroll
        for (int ks = 0; ks < 2; ks++) {
            const uint32_t ko = ks * 32;
            uint32_t bh[2][4], bl[2][4];
#pragma unroll
            for (int ng = 0; ng < 2; ng++) {
                if (ng < ngc) {
                    LDSM4(bh[ng], stage + BH_OFF + b_lm + ng * (16 * LDB) + ko);
                    LDSM4(bl[ng], stage + BL_OFF + b_lm + ng * (16 * LDB) + ko);
                }
            }
#pragma unroll
            for (int mt = 0; mt < 4; mt++) {
                uint32_t ah[4], al[4];
                LDSM4(ah, stage + AH_OFF + a_lm + mt * (16 * LDB) + ko);
                LDSM4(al, stage + AL_OFF + a_lm + mt * (16 * LDB) + ko);
#pragma unroll
                for (int nf = 0; nf < 4; nf++)
                    if (nf < nfc)
                        MMA_BF16(acc[mt][nf], ah,
                                 bh[nf >> 1][(nf & 1) * 2], bh[nf >> 1][(nf & 1) * 2 + 1]);
#pragma unroll
                for (int nf = 0; nf < 4; nf++)
                    if (nf < nfc)
                        MMA_BF16(acc[mt][nf], ah,
                                 bl[nf >> 1][(nf & 1) * 2], bl[nf >> 1][(nf & 1) * 2 + 1]);
#pragma unroll
                for (int nf = 0; nf < 4; nf++)
                    if (nf < nfc)
                        MMA_BF16(acc[mt][nf], al,
                                 bh[nf >> 1][(nf & 1) * 2], bh[nf >> 1][(nf & 1) * 2 + 1]);
            }
        }

        if (c + 1 < NCHUNK) {
            store_A(av, nstage);
            CP_WAIT0();
        }
        __syncthreads();
    }

    // ---- epilogue ----
#pragma unroll
    for (int mt = 0; mt < 4; mt++) {
        const int row = m0 + mw * 64 + mt * 16 + (lane >> 2);
#pragma unroll
        for (int nf = 0; nf < 4; nf++) {
            if (nf < nfc) {
                const int col = nw * 32 + nf * 8 + (lane & 3) * 2;
                if (col < K_) {
                    float2 v0 = {acc[mt][nf][0], acc[mt][nf][1]};
                    float2 v1 = {acc[mt][nf][2], acc[mt][nf][3]};
                    *reinterpret_cast<float2*>(out + ((size_t)row * G_ + g) * K_ + col) = v0;
                    *reinterpret_cast<float2*>(out + ((size_t)(row + 8) * G_ + g) * K_ + col) = v1;
                }
            }
        }
    }
}

// ---------------------------------------------------------------------------
extern "C" void kernel_launch(void* const* d_in, const int* in_sizes, int n_in,
                              void* d_out, int out_size) {
    const float* h = (const float*)d_in[0];   // [512,100,768]
    const float* w = (const float*)d_in[1];   // [100,768,100]
    float* out = (float*)d_out;               // [512,100,100]
    (void)in_sizes; (void)n_in; (void)out_size;

    const int smem_bytes = 2 * STAGE_BYTES;   // 81920 per CTA -> 2 CTAs/SM
    cudaFuncSetAttribute(gemm_hmma_kernel,
                         cudaFuncAttributeMaxDynamicSharedMemorySize, smem_bytes);

    norm_h_kernel<<<(B_ * G_) / 8, 256>>>(h);
    prep_w_kernel<<<G_, 256>>>(w);
    dim3 grid(B_ / 128, G_);
    gemm_hmma_kernel<<<grid, 256, smem_bytes>>>(h, out);
}

// round 9
// speedup vs baseline: 1.1560x; 1.0358x over previous
#include <cuda_runtime.h>
#include <cuda_bf16.h>
#include <cstdint>

// out[b,g,k] = sum_d (h[b,g,d]/||h||) * (w[g,d,k]/||w_col||)
// B=512, G=100, D=768, K=100.
// bf16 two-term split, 3-product HMMA, ldmatrix, double-buffered smem.
// R6 shape (128x128 CTA, 8 warps, warp 64x32, BKC=32, 2 CTAs/SM)
// + split-K x2 (blockIdx.z) into fp32 partials + reduce kernel.

#define B_ 512
#define G_ 100
#define D_ 768
#define K_ 100
#define KP 128
#define BKC 32              // k-chunk
#define NCHUNK 12           // chunks per split (24 total / 2 splits)
#define LDB 80              // smem row stride bytes (32 bf16 + pad)

#define AH_OFF 0
#define AL_OFF 10240
#define BH_OFF 20480
#define BL_OFF 30720
#define STAGE_BYTES 40960

// ---------------- device scratch ----------------
__device__ float g_inv_h[B_ * G_];
__device__ float g_inv_w[G_ * K_];
__device__ __nv_bfloat16 g_wt_hi[(size_t)G_ * KP * D_];
__device__ __nv_bfloat16 g_wt_lo[(size_t)G_ * KP * D_];
__device__ float g_part[2 * B_ * G_ * K_];   // split-K partials, 41MB

// ---------------- helpers ----------------
__device__ __forceinline__ uint32_t smem_u32(const void* p) {
    uint32_t a;
    asm("{ .reg .u64 t; cvta.to.shared.u64 t, %1; cvt.u32.u64 %0, t; }"
        : "=r"(a) : "l"(p));
    return a;
}

#define MMA_BF16(d, a, b0, b1)                                              \
    asm volatile(                                                           \
        "mma.sync.aligned.m16n8k16.row.col.f32.bf16.bf16.f32 "              \
        "{%0,%1,%2,%3}, {%4,%5,%6,%7}, {%8,%9}, {%0,%1,%2,%3};"             \
        : "+f"(d[0]), "+f"(d[1]), "+f"(d[2]), "+f"(d[3])                    \
        : "r"(a[0]), "r"(a[1]), "r"(a[2]), "r"(a[3]), "r"(b0), "r"(b1))

#define LDSM4(r, addr)                                                      \
    asm volatile("ldmatrix.sync.aligned.m8n8.x4.shared.b16 "                \
                 "{%0,%1,%2,%3}, [%4];"                                     \
                 : "=r"((r)[0]), "=r"((r)[1]), "=r"((r)[2]), "=r"((r)[3])   \
                 : "r"(addr))

#define CP16(dst, src)                                                      \
    asm volatile("cp.async.cg.shared.global [%0], [%1], 16;"                \
                 :: "r"(dst), "l"(src) : "memory")
#define CP_COMMIT() asm volatile("cp.async.commit_group;" ::: "memory")
#define CP_WAIT0()  asm volatile("cp.async.wait_group 0;" ::: "memory")

// ---------------------------------------------------------------------------
__global__ void norm_h_kernel(const float* __restrict__ h) {
    int warp = (blockIdx.x * blockDim.x + threadIdx.x) >> 5;
    int lane = threadIdx.x & 31;
    if (warp >= B_ * G_) return;
    const float4* p = reinterpret_cast<const float4*>(h + (size_t)warp * D_);
    float s = 0.f;
#pragma unroll
    for (int t = 0; t < 6; t++) {
        float4 v = p[lane + 32 * t];
        s += v.x * v.x + v.y * v.y + v.z * v.z + v.w * v.w;
    }
#pragma unroll
    for (int o = 16; o; o >>= 1) s += __shfl_xor_sync(0xffffffffu, s, o);
    if (lane == 0) g_inv_h[warp] = 1.0f / fmaxf(sqrtf(s), 1e-12f);
}

__global__ void norm_w_kernel(const float* __restrict__ w) {
    __shared__ float partial[4][128];
    int g = blockIdx.x;
    int k = threadIdx.x & 127;
    int c = threadIdx.x >> 7;
    float s = 0.f;
    if (k < K_) {
        const float* base = w + (size_t)g * D_ * K_ + (size_t)c * 192 * K_ + k;
#pragma unroll 8
        for (int d = 0; d < 192; d++) {
            float v = base[(size_t)d * K_];
            s += v * v;
        }
    }
    partial[c][k] = s;
    __syncthreads();
    if (c == 0 && k < K_) {
        float t = partial[0][k] + partial[1][k] + partial[2][k] + partial[3][k];
        g_inv_w[g * K_ + k] = 1.0f / fmaxf(sqrtf(t), 1e-12f);
    }
}

__global__ void split_w_kernel(const float* __restrict__ w) {
    __shared__ float ws[64][104];
    const int dc = blockIdx.x;
    const int g  = blockIdx.y;
    const int tid = threadIdx.x;
    const float* src = w + (size_t)g * D_ * K_ + (size_t)dc * 64 * K_;
#pragma unroll
    for (int i = 0; i < 25; i++) {
        int idx = tid + 256 * i;
        ws[idx / K_][idx % K_] = src[idx];
    }
    __syncthreads();
    const int k  = tid >> 1;
    const int d0 = (tid & 1) * 32;
    float invw = (k < K_) ? g_inv_w[g * K_ + k] : 0.f;
    __nv_bfloat16 hb[32], lb[32];
#pragma unroll
    for (int j = 0; j < 32; j++) {
        float x = (k < K_) ? ws[d0 + j][k] * invw : 0.f;
        __nv_bfloat16 hi = __float2bfloat16(x);
        hb[j] = hi;
        lb[j] = __float2bfloat16(x - __bfloat162float(hi));
    }
    size_t base = ((size_t)g * KP + k) * D_ + (size_t)dc * 64 + d0;
    uint4* dh = reinterpret_cast<uint4*>(g_wt_hi + base);
    uint4* dl = reinterpret_cast<uint4*>(g_wt_lo + base);
#pragma unroll
    for (int q = 0; q < 4; q++) {
        dh[q] = *reinterpret_cast<const uint4*>(hb + q * 8);
        dl[q] = *reinterpret_cast<const uint4*>(lb + q * 8);
    }
}

// ---------------------------------------------------------------------------
// HMMA GEMM, split-K x2. CTA = (g, 128 rows, k-half). 8 warps: mw = warp&1,
// nw = warp>>1. Warp tile 64x32, 3 bf16 products, fp32 acc.
// ---------------------------------------------------------------------------
__global__ __launch_bounds__(256, 2)
void gemm_hmma_kernel(const float* __restrict__ h) {
    extern __shared__ char smem[];
    const uint32_t sb = smem_u32(smem);
    const int tid  = threadIdx.x;
    const int lane = tid & 31;
    const int warp = tid >> 5;
    const int mw = warp & 1;
    const int nw = warp >> 1;
    const int g  = blockIdx.y;
    const int m0 = blockIdx.x * 128;
    const int kz = blockIdx.z;            // 0/1: which D-half
    const int c0 = kz * NCHUNK;           // starting chunk

    // ---- global load mapping: 2 threads per row, 16 elems each ----
    const int arow = tid >> 1;
    const int half = tid & 1;
    const float* gA = h + ((size_t)(m0 + arow) * G_ + g) * D_ + half * 16;
    const float invh = g_inv_h[(size_t)(m0 + arow) * G_ + g];
    const char* gBh = reinterpret_cast<const char*>(
        g_wt_hi + ((size_t)g * KP + arow) * D_) + half * 32;
    const char* gBl = reinterpret_cast<const char*>(
        g_wt_lo + ((size_t)g * KP + arow) * D_) + half * 32;

    const uint32_t srow = arow * LDB + half * 32;

    // ldmatrix base addresses (stage-relative)
    const uint32_t a_lm = (mw * 64 + (lane & 15)) * LDB + (lane >> 4) * 16;
    const uint32_t b_lm = (nw * 32 + (lane & 7) + ((lane >> 4) & 1) * 8) * LDB
                        + ((lane >> 3) & 1) * 16;

    float acc[4][4][4];   // [mt][nf][reg]
#pragma unroll
    for (int mt = 0; mt < 4; mt++)
#pragma unroll
        for (int nf = 0; nf < 4; nf++)
#pragma unroll
            for (int r = 0; r < 4; r++) acc[mt][nf][r] = 0.f;

    // ---- A convert+store: 16 fp32 -> hi/lo bf16 (32B each) ----
    auto store_A = [&](const float4* av, uint32_t stage) {
        uint32_t uh[8], ul[8];
#pragma unroll
        for (int i = 0; i < 4; i++) {
            float x0 = av[i].x * invh, x1 = av[i].y * invh;
            float x2 = av[i].z * invh, x3 = av[i].w * invh;
            __nv_bfloat162 h0 = __float22bfloat162_rn(make_float2(x0, x1));
            __nv_bfloat162 h1 = __float22bfloat162_rn(make_float2(x2, x3));
            float2 f0 = __bfloat1622float2(h0), f1 = __bfloat1622float2(h1);
            __nv_bfloat162 l0 = __float22bfloat162_rn(make_float2(x0 - f0.x, x1 - f0.y));
            __nv_bfloat162 l1 = __float22bfloat162_rn(make_float2(x2 - f1.x, x3 - f1.y));
            uh[i * 2]     = *reinterpret_cast<uint32_t*>(&h0);
            uh[i * 2 + 1] = *reinterpret_cast<uint32_t*>(&h1);
            ul[i * 2]     = *reinterpret_cast<uint32_t*>(&l0);
            ul[i * 2 + 1] = *reinterpret_cast<uint32_t*>(&l1);
        }
        asm volatile("st.shared.v4.b32 [%0], {%1,%2,%3,%4};"
            :: "r"(stage + AH_OFF + srow), "r"(uh[0]), "r"(uh[1]), "r"(uh[2]), "r"(uh[3]) : "memory");
        asm volatile("st.shared.v4.b32 [%0], {%1,%2,%3,%4};"
            :: "r"(stage + AH_OFF + srow + 16), "r"(uh[4]), "r"(uh[5]), "r"(uh[6]), "r"(uh[7]) : "memory");
        asm volatile("st.shared.v4.b32 [%0], {%1,%2,%3,%4};"
            :: "r"(stage + AL_OFF + srow), "r"(ul[0]), "r"(ul[1]), "r"(ul[2]), "r"(ul[3]) : "memory");
        asm volatile("st.shared.v4.b32 [%0], {%1,%2,%3,%4};"
            :: "r"(stage + AL_OFF + srow + 16), "r"(ul[4]), "r"(ul[5]), "r"(ul[6]), "r"(ul[7]) : "memory");
    };

    auto cp_B = [&](int c, uint32_t stage) {
        CP16(stage + BH_OFF + srow,      gBh + (size_t)c * 64);
        CP16(stage + BH_OFF + srow + 16, gBh + (size_t)c * 64 + 16);
        CP16(stage + BL_OFF + srow,      gBl + (size_t)c * 64);
        CP16(stage + BL_OFF + srow + 16, gBl + (size_t)c * 64 + 16);
    };

    // ---- prologue: fill stage 0 ----
    {
        float4 av[4];
#pragma unroll
        for (int i = 0; i < 4; i++)
            av[i] = *reinterpret_cast<const float4*>(gA + c0 * BKC + i * 4);
        cp_B(c0, sb);
        CP_COMMIT();
        store_A(av, sb);
        CP_WAIT0();
    }
    __syncthreads();

    for (int cc = 0; cc < NCHUNK; cc++) {
        const int c = c0 + cc;
        const uint32_t stage  = sb + (uint32_t)(cc & 1) * STAGE_BYTES;
        const uint32_t nstage = sb + (uint32_t)((cc + 1) & 1) * STAGE_BYTES;

        float4 av[4];
        if (cc + 1 < NCHUNK) {
#pragma unroll
            for (int i = 0; i < 4; i++)
                av[i] = *reinterpret_cast<const float4*>(gA + (c + 1) * BKC + i * 4);
            cp_B(c + 1, nstage);
            CP_COMMIT();
        }

        // ---- compute current chunk: 2 k16-steps ----
#pragma unroll
        for (int ks = 0; ks < 2; ks++) {
            const uint32_t ko = ks * 32;
            uint32_t bh[2][4], bl[2][4];
#pragma unroll
            for (int ng = 0; ng < 2; ng++) {
                LDSM4(bh[ng], stage + BH_OFF + b_lm + ng * (16 * LDB) + ko);
                LDSM4(bl[ng], stage + BL_OFF + b_lm + ng * (16 * LDB) + ko);
            }
#pragma unroll
            for (int mt = 0; mt < 4; mt++) {
                uint32_t ah[4], al[4];
                LDSM4(ah, stage + AH_OFF + a_lm + mt * (16 * LDB) + ko);
                LDSM4(al, stage + AL_OFF + a_lm + mt * (16 * LDB) + ko);
#pragma unroll
                for (int nf = 0; nf < 4; nf++)
                    MMA_BF16(acc[mt][nf], ah,
                             bh[nf >> 1][(nf & 1) * 2], bh[nf >> 1][(nf & 1) * 2 + 1]);
#pragma unroll
                for (int nf = 0; nf < 4; nf++)
                    MMA_BF16(acc[mt][nf], ah,
                             bl[nf >> 1][(nf & 1) * 2], bl[nf >> 1][(nf & 1) * 2 + 1]);
#pragma unroll
                for (int nf = 0; nf < 4; nf++)
                    MMA_BF16(acc[mt][nf], al,
                             bh[nf >> 1][(nf & 1) * 2], bh[nf >> 1][(nf & 1) * 2 + 1]);
            }
        }

        if (cc + 1 < NCHUNK) {
            store_A(av, nstage);
            CP_WAIT0();
        }
        __syncthreads();
    }

    // ---- epilogue: write split partial ----
    float* part = g_part + (size_t)kz * (B_ * G_ * K_);
#pragma unroll
    for (int mt = 0; mt < 4; mt++) {
        const int row = m0 + mw * 64 + mt * 16 + (lane >> 2);
#pragma unroll
        for (int nf = 0; nf < 4; nf++) {
            const int col = nw * 32 + nf * 8 + (lane & 3) * 2;
            if (col < K_) {
                float2 v0 = {acc[mt][nf][0], acc[mt][nf][1]};
                float2 v1 = {acc[mt][nf][2], acc[mt][nf][3]};
                *reinterpret_cast<float2*>(part + ((size_t)row * G_ + g) * K_ + col) = v0;
                *reinterpret_cast<float2*>(part + ((size_t)(row + 8) * G_ + g) * K_ + col) = v1;
            }
        }
    }
}

// ---------------------------------------------------------------------------
// Reduce: out = part0 + part1 (float4 vectorized; 5.12M floats).
// ---------------------------------------------------------------------------
__global__ void reduce_kernel(float* __restrict__ out) {
    int i = blockIdx.x * blockDim.x + threadIdx.x;   // float4 index
    const int n4 = (B_ * G_ * K_) / 4;               // 1,280,000
    if (i < n4) {
        const float4* p0 = reinterpret_cast<const float4*>(g_part);
        const float4* p1 = reinterpret_cast<const float4*>(g_part + B_ * G_ * K_);
        float4 a = p0[i], b = p1[i];
        float4 r = {a.x + b.x, a.y + b.y, a.z + b.z, a.w + b.w};
        reinterpret_cast<float4*>(out)[i] = r;
    }
}

// ---------------------------------------------------------------------------
extern "C" void kernel_launch(void* const* d_in, const int* in_sizes, int n_in,
                              void* d_out, int out_size) {
    const float* h = (const float*)d_in[0];   // [512,100,768]
    const float* w = (const float*)d_in[1];   // [100,768,100]
    float* out = (float*)d_out;               // [512,100,100]
    (void)in_sizes; (void)n_in; (void)out_size;

    const int smem_bytes = 2 * STAGE_BYTES;   // 81920 per CTA -> 2 CTAs/SM
    cudaFuncSetAttribute(gemm_hmma_kernel,
                         cudaFuncAttributeMaxDynamicSharedMemorySize, smem_bytes);

    norm_h_kernel<<<(B_ * G_) / 8, 256>>>(h);
    norm_w_kernel<<<G_, 512>>>(w);
    split_w_kernel<<<dim3(12, G_), 256>>>(w);
    dim3 grid(B_ / 128, G_, 2);
    gemm_hmma_kernel<<<grid, 256, smem_bytes>>>(h);
    reduce_kernel<<<(B_ * G_ * K_ / 4 + 255) / 256, 256>>>(out);
}